// round 10
// baseline (speedup 1.0000x reference)
#include <cuda_runtime.h>
#include <cuda_bf16.h>
#include <cstdint>

// Static scratch (no allocations allowed). Sized for V <= 4M, n_he <= 8M.
__device__ int g_counts[4u << 20];      // histogram / per-vertex valence
__device__ int g_offsets[4u << 20];     // block-local exclusive offsets
__device__ int g_blocksums[4096];       // global exclusive block offsets
__device__ int g_rank[8u << 20];        // within-vertex rank of each edge
__device__ int g_perm[8u << 20];        // edge indices grouped by vertex (dense)

// ---------------------------------------------------------------------------
// Warp-shuffle inclusive scan helper.
// ---------------------------------------------------------------------------
__device__ __forceinline__ int warp_incl_scan(int v)
{
    #pragma unroll
    for (int d = 1; d < 32; d <<= 1) {
        int t = __shfl_up_sync(0xffffffffu, v, d);
        if ((threadIdx.x & 31) >= d) v += t;
    }
    return v;
}

// ---------------------------------------------------------------------------
// Pass A: histogram + per-edge rank (atomic return value kept, written int4-
// coalesced) so placement needs no atomics.
// ---------------------------------------------------------------------------
__global__ void rank_hist_kernel(const int4* __restrict__ ids4, int nq,
                                 const int* __restrict__ ids, int n)
{
    int i = blockIdx.x * blockDim.x + threadIdx.x;
    if (i < nq) {
        int4 v = __ldg(ids4 + i);
        int4 r;
        r.x = atomicAdd(&g_counts[v.x], 1);
        r.y = atomicAdd(&g_counts[v.y], 1);
        r.z = atomicAdd(&g_counts[v.z], 1);
        r.w = atomicAdd(&g_counts[v.w], 1);
        ((int4*)g_rank)[i] = r;
    }
    if (i == 0) {
        for (int j = nq * 4; j < n; j++)
            g_rank[j] = atomicAdd(&g_counts[__ldg(ids + j)], 1);
    }
}

// ---------------------------------------------------------------------------
// Scan step 1: per-block (1024) exclusive scan of counts; block totals out.
// ---------------------------------------------------------------------------
__global__ void scan1_kernel(int V)
{
    __shared__ int wsum[32];
    int i = blockIdx.x * 1024 + threadIdx.x;
    int v = (i < V) ? g_counts[i] : 0;
    int incl = warp_incl_scan(v);
    int lane = threadIdx.x & 31, wid = threadIdx.x >> 5;
    if (lane == 31) wsum[wid] = incl;
    __syncthreads();
    if (wid == 0) {
        int w = wsum[lane];
        int ws = warp_incl_scan(w);
        wsum[lane] = ws - w;                  // exclusive warp offsets
    }
    __syncthreads();
    int excl = incl - v + wsum[wid];
    if (i < V) g_offsets[i] = excl;
    if (threadIdx.x == 1023) g_blocksums[blockIdx.x] = excl + v;   // block total
}

// ---------------------------------------------------------------------------
// Scan step 2: single-block exclusive scan of block sums (carry loop).
// ---------------------------------------------------------------------------
__global__ void scan2_kernel(int nb)
{
    __shared__ int wsum[32];
    __shared__ int carry_s;
    if (threadIdx.x == 0) carry_s = 0;
    __syncthreads();
    for (int base = 0; base < nb; base += 1024) {
        int i = base + threadIdx.x;
        int v = (i < nb) ? g_blocksums[i] : 0;
        int incl = warp_incl_scan(v);
        int lane = threadIdx.x & 31, wid = threadIdx.x >> 5;
        if (lane == 31) wsum[wid] = incl;
        __syncthreads();
        if (wid == 0) {
            int w = wsum[lane];
            int ws = warp_incl_scan(w);
            wsum[lane] = ws - w;
        }
        __syncthreads();
        int excl = incl - v + wsum[wid] + carry_s;
        if (i < nb) g_blocksums[i] = excl;
        __syncthreads();
        if (threadIdx.x == 1023) carry_s = excl + v;
        __syncthreads();
    }
}

// ---------------------------------------------------------------------------
// Pass B: atomic-free placement. pos = global offset of v + precomputed rank.
// ---------------------------------------------------------------------------
__global__ void place_kernel(const int4* __restrict__ ids4, int nq,
                             const int* __restrict__ ids, int n)
{
    int i = blockIdx.x * blockDim.x + threadIdx.x;
    if (i < nq) {
        int4 v = __ldg(ids4 + i);
        int4 r = __ldg(((const int4*)g_rank) + i);
        int p0 = __ldg(&g_offsets[v.x]) + __ldg(&g_blocksums[v.x >> 10]) + r.x;
        int p1 = __ldg(&g_offsets[v.y]) + __ldg(&g_blocksums[v.y >> 10]) + r.y;
        int p2 = __ldg(&g_offsets[v.z]) + __ldg(&g_blocksums[v.z >> 10]) + r.z;
        int p3 = __ldg(&g_offsets[v.w]) + __ldg(&g_blocksums[v.w >> 10]) + r.w;
        g_perm[p0] = i * 4;
        g_perm[p1] = i * 4 + 1;
        g_perm[p2] = i * 4 + 2;
        g_perm[p3] = i * 4 + 3;
    }
    if (i == 0) {
        for (int j = nq * 4; j < n; j++) {
            int v = __ldg(ids + j);
            int p = __ldg(&g_offsets[v]) + __ldg(&g_blocksums[v >> 10]) + g_rank[j];
            g_perm[p] = j;
        }
    }
}

// ---------------------------------------------------------------------------
// Pass C: gather + mean. 8 threads per vertex; thread s covers feature quad s
// as one float4 (8-thread group = one 128B edge row per load).
// Index fetch is VECTORIZED: each thread loads the segment's perm entries as
// aligned int4 quads (2 x LDG.128 per 8-edge chunk instead of 8 x LDG.32),
// keeping the load->load address chain (no shuffle hop) at 1/4 the index
// issue traffic. Entries are predicated on beg <= j < end.
// ---------------------------------------------------------------------------
__global__ void __launch_bounds__(256)
gather_kernel(const float4* __restrict__ x4, float4* __restrict__ out4,
              int V, int n_he)
{
    long long t = (long long)blockIdx.x * blockDim.x + threadIdx.x;
    int v = (int)(t >> 3);          // vertex
    int s = (int)(t & 7);           // quad index within the 32-dim row
    if (v >= V) return;

    int beg = __ldg(&g_offsets[v]) + __ldg(&g_blocksums[v >> 10]);
    int end = (v + 1 < V)
            ? __ldg(&g_offsets[v + 1]) + __ldg(&g_blocksums[(v + 1) >> 10])
            : n_he;
    int deg = end - beg;

    unsigned long long pol;
    asm("createpolicy.fractional.L2::evict_first.b64 %0, 1.0;" : "=l"(pol));

    const int4* perm4 = (const int4*)g_perm;
    float4 acc = make_float4(0.f, 0.f, 0.f, 0.f);

    for (int q = beg >> 2; q * 4 < end; q += 2) {
        int4 a = __ldg(perm4 + q);
        int4 b = ((q + 1) * 4 < end) ? __ldg(perm4 + q + 1)
                                     : make_int4(0, 0, 0, 0);
        int e[8] = { a.x, a.y, a.z, a.w, b.x, b.y, b.z, b.w };
        int j0 = q * 4;
        #pragma unroll
        for (int u = 0; u < 8; u++) {
            int j = j0 + u;
            if (j >= beg && j < end) {
                float4 r;
                asm("ld.global.nc.L2::cache_hint.v4.f32 {%0, %1, %2, %3}, [%4], %5;"
                    : "=f"(r.x), "=f"(r.y), "=f"(r.z), "=f"(r.w)
                    : "l"(x4 + (long long)e[u] * 8 + s), "l"(pol));
                acc.x += r.x; acc.y += r.y; acc.z += r.z; acc.w += r.w;
            }
        }
    }

    float inv = 1.0f / fmaxf((float)deg, 1.0f);
    out4[(long long)v * 8 + s] =
        make_float4(acc.x * inv, acc.y * inv, acc.z * inv, acc.w * inv);
}

extern "C" void kernel_launch(void* const* d_in, const int* in_sizes, int n_in,
                              void* d_out, int out_size)
{
    const float4* x4  = (const float4*)d_in[0];
    const int*    ids = (const int*)d_in[1];

    int n_he = in_sizes[1];                     // element count of vertex_ids
    int V    = (int)((long long)out_size / 32); // output is [V, 32]
    int nq   = n_he >> 2;                       // int4 quads in the id stream

    // Zero the histogram.
    void* counts_ptr = nullptr;
    cudaGetSymbolAddress(&counts_ptr, g_counts);
    cudaMemsetAsync(counts_ptr, 0, (size_t)V * sizeof(int));

    // Pass A: histogram + ranks (the only atomic pass).
    rank_hist_kernel<<<(nq + 255) / 256, 256>>>((const int4*)ids, nq, ids, n_he);

    // Exclusive scan: block-local offsets + global block offsets.
    int nb = (V + 1023) / 1024;
    scan1_kernel<<<nb, 1024>>>(V);
    scan2_kernel<<<1, 1024>>>(nb);

    // Pass B: atomic-free placement.
    place_kernel<<<(nq + 255) / 256, 256>>>((const int4*)ids, nq, ids, n_he);

    // Pass C: gather + mean, 8 threads per vertex, vectorized index fetch.
    {
        long long total = (long long)V * 8;
        int threads = 256;
        int blocks = (int)((total + threads - 1) / threads);
        gather_kernel<<<blocks, threads>>>(x4, (float4*)d_out, V, n_he);
    }
}

// round 11
// speedup vs baseline: 1.1159x; 1.1159x over previous
#include <cuda_runtime.h>
#include <cuda_bf16.h>
#include <cstdint>

// Static scratch (no allocations allowed). Sized for V <= 4M, n_he <= 8M.
__device__ int g_counts[4u << 20];      // histogram
__device__ int g_offsets[4u << 20];     // block-local excl offsets -> incl ends
__device__ int g_blocksums[1024];       // global excl offsets of 4096-v blocks
__device__ int g_perm[8u << 20];        // edge indices grouped by vertex

// ---------------------------------------------------------------------------
// Warp-shuffle inclusive scan helper.
// ---------------------------------------------------------------------------
__device__ __forceinline__ int warp_incl_scan(int v)
{
    #pragma unroll
    for (int d = 1; d < 32; d <<= 1) {
        int t = __shfl_up_sync(0xffffffffu, v, d);
        if ((threadIdx.x & 31) >= d) v += t;
    }
    return v;
}

// ---------------------------------------------------------------------------
// Pass A: histogram of vertex ids (int4-vectorized id stream).
// ---------------------------------------------------------------------------
__global__ void hist_kernel(const int4* __restrict__ ids4, int nq,
                            const int* __restrict__ ids, int n)
{
    int i = blockIdx.x * blockDim.x + threadIdx.x;
    if (i < nq) {
        int4 v = __ldg(ids4 + i);
        atomicAdd(&g_counts[v.x], 1);
        atomicAdd(&g_counts[v.y], 1);
        atomicAdd(&g_counts[v.z], 1);
        atomicAdd(&g_counts[v.w], 1);
    }
    if (i == 0) {
        for (int j = nq * 4; j < n; j++) atomicAdd(&g_counts[__ldg(ids + j)], 1);
    }
}

// ---------------------------------------------------------------------------
// Scan step 1: per-block exclusive scan over 4096 counts (int4 per thread,
// 1024 threads). g_offsets gets BLOCK-LOCAL exclusive offsets; block totals
// go to g_blocksums.
// ---------------------------------------------------------------------------
__global__ void scan1_kernel(int V)
{
    __shared__ int wsum[32];
    int i0 = blockIdx.x * 4096 + threadIdx.x * 4;

    int4 c = make_int4(0, 0, 0, 0);
    if (i0 + 3 < V) {
        c = *(const int4*)(g_counts + i0);
    } else {
        if (i0 + 0 < V) c.x = g_counts[i0 + 0];
        if (i0 + 1 < V) c.y = g_counts[i0 + 1];
        if (i0 + 2 < V) c.z = g_counts[i0 + 2];
        if (i0 + 3 < V) c.w = g_counts[i0 + 3];
    }
    int ts = c.x + c.y + c.z + c.w;

    int incl = warp_incl_scan(ts);
    int lane = threadIdx.x & 31, wid = threadIdx.x >> 5;
    if (lane == 31) wsum[wid] = incl;
    __syncthreads();
    if (wid == 0) {
        int w = wsum[lane];
        int ws = warp_incl_scan(w);
        wsum[lane] = ws - w;                  // exclusive warp offsets
    }
    __syncthreads();
    int excl = incl - ts + wsum[wid];

    int4 o;
    o.x = excl;
    o.y = o.x + c.x;
    o.z = o.y + c.y;
    o.w = o.z + c.z;
    if (i0 + 3 < V) {
        *(int4*)(g_offsets + i0) = o;
    } else {
        if (i0 + 0 < V) g_offsets[i0 + 0] = o.x;
        if (i0 + 1 < V) g_offsets[i0 + 1] = o.y;
        if (i0 + 2 < V) g_offsets[i0 + 2] = o.z;
        if (i0 + 3 < V) g_offsets[i0 + 3] = o.w;
    }
    if (threadIdx.x == 1023) g_blocksums[blockIdx.x] = excl + ts;  // block total
}

// ---------------------------------------------------------------------------
// Scan step 2: single-block exclusive scan of block sums (one iteration for
// nb <= 1024, which holds for V <= 4M).
// ---------------------------------------------------------------------------
__global__ void scan2_kernel(int nb)
{
    __shared__ int wsum[32];
    __shared__ int carry_s;
    if (threadIdx.x == 0) carry_s = 0;
    __syncthreads();
    for (int base = 0; base < nb; base += 1024) {
        int i = base + threadIdx.x;
        int v = (i < nb) ? g_blocksums[i] : 0;
        int incl = warp_incl_scan(v);
        int lane = threadIdx.x & 31, wid = threadIdx.x >> 5;
        if (lane == 31) wsum[wid] = incl;
        __syncthreads();
        if (wid == 0) {
            int w = wsum[lane];
            int ws = warp_incl_scan(w);
            wsum[lane] = ws - w;
        }
        __syncthreads();
        int excl = incl - v + wsum[wid] + carry_s;
        if (i < nb) g_blocksums[i] = excl;
        __syncthreads();
        if (threadIdx.x == 1023) carry_s = excl + v;
        __syncthreads();
    }
}

// ---------------------------------------------------------------------------
// Pass B: counting-sort of edge INDICES by vertex id (scalar returning atomic
// per edge — measured at its L2-atomic floor). Global position = block-local
// cursor bump + global 4096-block offset (<=1KB table, L1-resident).
// Post: g_offsets[v] == block-local inclusive end of segment v.
// ---------------------------------------------------------------------------
__global__ void perm_kernel(const int* __restrict__ ids, int n)
{
    int i = blockIdx.x * blockDim.x + threadIdx.x;
    if (i < n) {
        int v = __ldg(ids + i);
        int pos = atomicAdd(&g_offsets[v], 1) + __ldg(&g_blocksums[v >> 12]);
        g_perm[pos] = i;
    }
}

// ---------------------------------------------------------------------------
// Pass C: gather + mean (measured-best R7 form). 8 threads per vertex;
// thread s covers feature quad s as one float4 (group = one 128B row/load).
// Per 8-edge chunk every thread loads all 8 perm entries (1 fetch + 7
// L1-broadcast hits) -> load->load address chain, no shuffle hop; the 8 row
// loads are independent (high MLP); no serial tail for deg <= 8.
// ---------------------------------------------------------------------------
__global__ void gather_kernel(const float4* __restrict__ x4,
                              float4* __restrict__ out4, int V)
{
    long long t = (long long)blockIdx.x * blockDim.x + threadIdx.x;
    int v = (int)(t >> 3);          // vertex
    int s = (int)(t & 7);           // quad index within the 32-dim row
    if (v >= V) return;

    int beg = (v == 0) ? 0
            : __ldg(&g_offsets[v - 1]) + __ldg(&g_blocksums[(v - 1) >> 12]);
    int end = __ldg(&g_offsets[v]) + __ldg(&g_blocksums[v >> 12]);
    int deg = end - beg;

    float4 acc = make_float4(0.f, 0.f, 0.f, 0.f);

    for (int base = beg; base < end; base += 8) {
        int e[8];
        #pragma unroll
        for (int u = 0; u < 8; u++) {
            int j = base + u;
            e[u] = (j < end) ? __ldg(&g_perm[j]) : -1;
        }
        #pragma unroll
        for (int u = 0; u < 8; u++) {
            if (e[u] >= 0) {
                float4 a = __ldg(x4 + (long long)e[u] * 8 + s);
                acc.x += a.x; acc.y += a.y; acc.z += a.z; acc.w += a.w;
            }
        }
    }

    float inv = 1.0f / fmaxf((float)deg, 1.0f);
    out4[(long long)v * 8 + s] =
        make_float4(acc.x * inv, acc.y * inv, acc.z * inv, acc.w * inv);
}

extern "C" void kernel_launch(void* const* d_in, const int* in_sizes, int n_in,
                              void* d_out, int out_size)
{
    const float4* x4  = (const float4*)d_in[0];
    const int*    ids = (const int*)d_in[1];

    int n_he = in_sizes[1];                     // element count of vertex_ids
    int V    = (int)((long long)out_size / 32); // output is [V, 32]
    int nq   = n_he >> 2;                       // int4 quads in the id stream

    // Zero the histogram.
    void* counts_ptr = nullptr;
    cudaGetSymbolAddress(&counts_ptr, g_counts);
    cudaMemsetAsync(counts_ptr, 0, (size_t)V * sizeof(int));

    // Pass A: histogram (vectorized id stream).
    hist_kernel<<<(nq + 255) / 256, 256>>>((const int4*)ids, nq, ids, n_he);

    // Exclusive scan: 4096-wide blocks, single-iteration top scan.
    int nb = (V + 4095) / 4096;
    scan1_kernel<<<nb, 1024>>>(V);
    scan2_kernel<<<1, 1024>>>(nb);

    // Pass B: permutation (scalar atomics, blocksums folded in).
    perm_kernel<<<(n_he + 255) / 256, 256>>>(ids, n_he);

    // Pass C: gather + mean, 8 threads per vertex.
    {
        long long total = (long long)V * 8;
        int threads = 256;
        int blocks = (int)((total + threads - 1) / threads);
        gather_kernel<<<blocks, threads>>>(x4, (float4*)d_out, V);
    }
}